// round 15
// baseline (speedup 1.0000x reference)
#include <cuda_runtime.h>

// RotationPerturbationLayer == bilinear sampling with zero padding (the dense
// [B,N,N] tent-weight einsum has <=4 nonzero taps per output coordinate;
// taps outside [0,W)x[0,H) contribute zero).
//
// R14 == R9 champion, reinstated (best measured: 6.24us total / 5.02us
// kernel / 26 regs). Full search matrix concluded:
//   - nested per-tap ifs beat branch-free and hybrid predication
//   - 1 pixel/thread beats 2 and 4 px/thread coarsening
//   - 128 CTAs x 256 threads beats 256x128 and 32x256
//   - chain trims (float2int_rd, explicit fmaf, folded output offset) won
// Kernel is launch/ramp-floor-bound (DRAM 0.1%, issue ~6%); no further
// code-side lever exists at this problem size.

#define BB 8
#define CC 3
#define HH 64
#define WW 64
#define NN (HH * WW)   // 4096

__global__ __launch_bounds__(256, 1)
void rotation_bilinear_kernel(const float* __restrict__ theta,
                              const float* __restrict__ image,
                              float* __restrict__ out)
{
    const int idx = blockIdx.x * blockDim.x + threadIdx.x;  // 0 .. B*N-1
    const int b = idx >> 12;        // / NN
    const int n = idx & (NN - 1);   // % NN
    const int y = n >> 6;           // / WW
    const int x = n & (WW - 1);     // % WW

    const float t = __ldg(theta + b);   // 8 distinct values, L2-broadcast
    float st, ct;
    __sincosf(t, &st, &ct);

    const float c_x = (WW - 1) * 0.5f;
    const float c_y = (HH - 1) * 0.5f;
    const float xr = (float)x - c_x;
    const float yr = (float)y - c_y;

    const float sx = fmaf(ct, xr, fmaf(st, yr, c_x));
    const float sy = fmaf(-st, xr, fmaf(ct, yr, c_y));

    const int x0 = __float2int_rd(sx);
    const int y0 = __float2int_rd(sy);
    const int x1 = x0 + 1;
    const int y1 = y0 + 1;

    const float ax = sx - (float)x0;   // tent weight toward x1
    const float ay = sy - (float)y0;
    const float bx = 1.0f - ax;        // tent weight toward x0
    const float by = 1.0f - ay;

    const bool vx0 = (unsigned)x0 < (unsigned)WW;
    const bool vx1 = (unsigned)x1 < (unsigned)WW;
    const bool vy0 = (unsigned)y0 < (unsigned)HH;
    const bool vy1 = (unsigned)y1 < (unsigned)HH;

    const float* img1 = image + NN;
    const float* img2 = image + 2 * NN;

    float acc0 = 0.0f, acc1 = 0.0f, acc2 = 0.0f;

    if (vy0) {
        const int row = y0 * WW;
        if (vx0) {
            const float w = by * bx;
            const int p = row + x0;
            acc0 = fmaf(w, __ldg(image + p), acc0);
            acc1 = fmaf(w, __ldg(img1 + p),  acc1);
            acc2 = fmaf(w, __ldg(img2 + p),  acc2);
        }
        if (vx1) {
            const float w = by * ax;
            const int p = row + x1;
            acc0 = fmaf(w, __ldg(image + p), acc0);
            acc1 = fmaf(w, __ldg(img1 + p),  acc1);
            acc2 = fmaf(w, __ldg(img2 + p),  acc2);
        }
    }
    if (vy1) {
        const int row = y1 * WW;
        if (vx0) {
            const float w = ay * bx;
            const int p = row + x0;
            acc0 = fmaf(w, __ldg(image + p), acc0);
            acc1 = fmaf(w, __ldg(img1 + p),  acc1);
            acc2 = fmaf(w, __ldg(img2 + p),  acc2);
        }
        if (vx1) {
            const float w = ay * ax;
            const int p = row + x1;
            acc0 = fmaf(w, __ldg(image + p), acc0);
            acc1 = fmaf(w, __ldg(img1 + p),  acc1);
            acc2 = fmaf(w, __ldg(img2 + p),  acc2);
        }
    }

    // out [B, C, H, W]: offset = b*3*NN + n = idx + b*2*NN = idx + (b << 13)
    float* ob = out + idx + (b << 13);
    ob[0]      = acc0;
    ob[NN]     = acc1;
    ob[2 * NN] = acc2;
}

extern "C" void kernel_launch(void* const* d_in, const int* in_sizes, int n_in,
                              void* d_out, int out_size)
{
    const float* theta = (const float*)d_in[0];  // [B,1] = 8 floats
    const float* image = (const float*)d_in[1];  // [C,H,W] = 12288 floats
    float* out = (float*)d_out;                  // [B,C,H,W] = 98304 floats

    // 32768 threads = 128 blocks x 256 -> single wave, champion shape.
    rotation_bilinear_kernel<<<(BB * NN) / 256, 256>>>(theta, image, out);
}

// round 16
// speedup vs baseline: 1.0386x; 1.0386x over previous
#include <cuda_runtime.h>

// RotationPerturbationLayer == bilinear sampling with zero padding (the dense
// [B,N,N] tent-weight einsum has <=4 nonzero taps per output coordinate;
// taps outside [0,W)x[0,H) contribute zero).
//
// FINAL (== R9/R14 champion). Best measured: 5.02us kernel / 26 regs;
// end-to-end timer noise is +-0.3-0.6us (identical source scored both 6.24
// and 6.88). Search matrix closed:
//   - nested per-tap ifs beat branch-free and hybrid predication
//   - 1 pixel/thread beats 2 and 4 px/thread coarsening
//   - 128 CTAs x 256 threads beats 256x128 and 32x256
//   - chain trims (float2int_rd, explicit fmaf, folded output offset) won
// Kernel is launch/ramp-floor-bound (DRAM 0.1%, issue ~6%).

#define BB 8
#define CC 3
#define HH 64
#define WW 64
#define NN (HH * WW)   // 4096

__global__ __launch_bounds__(256, 1)
void rotation_bilinear_kernel(const float* __restrict__ theta,
                              const float* __restrict__ image,
                              float* __restrict__ out)
{
    const int idx = blockIdx.x * blockDim.x + threadIdx.x;  // 0 .. B*N-1
    const int b = idx >> 12;        // / NN
    const int n = idx & (NN - 1);   // % NN
    const int y = n >> 6;           // / WW
    const int x = n & (WW - 1);     // % WW

    const float t = __ldg(theta + b);   // 8 distinct values, L2-broadcast
    float st, ct;
    __sincosf(t, &st, &ct);

    const float c_x = (WW - 1) * 0.5f;
    const float c_y = (HH - 1) * 0.5f;
    const float xr = (float)x - c_x;
    const float yr = (float)y - c_y;

    const float sx = fmaf(ct, xr, fmaf(st, yr, c_x));
    const float sy = fmaf(-st, xr, fmaf(ct, yr, c_y));

    const int x0 = __float2int_rd(sx);
    const int y0 = __float2int_rd(sy);
    const int x1 = x0 + 1;
    const int y1 = y0 + 1;

    const float ax = sx - (float)x0;   // tent weight toward x1
    const float ay = sy - (float)y0;
    const float bx = 1.0f - ax;        // tent weight toward x0
    const float by = 1.0f - ay;

    const bool vx0 = (unsigned)x0 < (unsigned)WW;
    const bool vx1 = (unsigned)x1 < (unsigned)WW;
    const bool vy0 = (unsigned)y0 < (unsigned)HH;
    const bool vy1 = (unsigned)y1 < (unsigned)HH;

    const float* img1 = image + NN;
    const float* img2 = image + 2 * NN;

    float acc0 = 0.0f, acc1 = 0.0f, acc2 = 0.0f;

    if (vy0) {
        const int row = y0 * WW;
        if (vx0) {
            const float w = by * bx;
            const int p = row + x0;
            acc0 = fmaf(w, __ldg(image + p), acc0);
            acc1 = fmaf(w, __ldg(img1 + p),  acc1);
            acc2 = fmaf(w, __ldg(img2 + p),  acc2);
        }
        if (vx1) {
            const float w = by * ax;
            const int p = row + x1;
            acc0 = fmaf(w, __ldg(image + p), acc0);
            acc1 = fmaf(w, __ldg(img1 + p),  acc1);
            acc2 = fmaf(w, __ldg(img2 + p),  acc2);
        }
    }
    if (vy1) {
        const int row = y1 * WW;
        if (vx0) {
            const float w = ay * bx;
            const int p = row + x0;
            acc0 = fmaf(w, __ldg(image + p), acc0);
            acc1 = fmaf(w, __ldg(img1 + p),  acc1);
            acc2 = fmaf(w, __ldg(img2 + p),  acc2);
        }
        if (vx1) {
            const float w = ay * ax;
            const int p = row + x1;
            acc0 = fmaf(w, __ldg(image + p), acc0);
            acc1 = fmaf(w, __ldg(img1 + p),  acc1);
            acc2 = fmaf(w, __ldg(img2 + p),  acc2);
        }
    }

    // out [B, C, H, W]: offset = b*3*NN + n = idx + b*2*NN = idx + (b << 13)
    float* ob = out + idx + (b << 13);
    ob[0]      = acc0;
    ob[NN]     = acc1;
    ob[2 * NN] = acc2;
}

extern "C" void kernel_launch(void* const* d_in, const int* in_sizes, int n_in,
                              void* d_out, int out_size)
{
    const float* theta = (const float*)d_in[0];  // [B,1] = 8 floats
    const float* image = (const float*)d_in[1];  // [C,H,W] = 12288 floats
    float* out = (float*)d_out;                  // [B,C,H,W] = 98304 floats

    // 32768 threads = 128 blocks x 256 -> single wave, champion shape.
    rotation_bilinear_kernel<<<(BB * NN) / 256, 256>>>(theta, image, out);
}